// round 1
// baseline (speedup 1.0000x reference)
#include <cuda_runtime.h>
#include <stdint.h>

#define BATCH 4096
#define INDIM 1024
#define OUTDIM 1024
#define NNZ_MAX 65536

// -------- device scratch (static; no allocations allowed) --------
__device__ float g_inT[(size_t)INDIM * BATCH];   // transposed input, 16MB
__device__ uint2 g_meta[NNZ_MAX];                // per-nnz {weight bits, ind_in}, CSR-ordered by out col
__device__ int   g_cnt[OUTDIM];
__device__ int   g_offs[OUTDIM + 1];
__device__ int   g_cur[OUTDIM];

// -------- 1. zero counters --------
__global__ void k_zero() {
    int t = threadIdx.x;
    g_cnt[t] = 0;
    g_cur[t] = 0;
}

// -------- 2. histogram of ind_out --------
__global__ void k_hist(const int* __restrict__ ind_out, int nnz) {
    int i = blockIdx.x * blockDim.x + threadIdx.x;
    if (i < nnz) atomicAdd(&g_cnt[ind_out[i]], 1);
}

// -------- 3. exclusive scan over 1024 counts (one CTA) --------
__global__ void k_scan() {
    __shared__ int wsum[32];
    int t = threadIdx.x;
    int lane = t & 31, wid = t >> 5;
    int c = g_cnt[t];
    int v = c;
#pragma unroll
    for (int d = 1; d < 32; d <<= 1) {
        int n = __shfl_up_sync(0xffffffffu, v, d);
        if (lane >= d) v += n;
    }
    if (lane == 31) wsum[wid] = v;
    __syncthreads();
    if (wid == 0) {
        int s = wsum[lane];
#pragma unroll
        for (int d = 1; d < 32; d <<= 1) {
            int n = __shfl_up_sync(0xffffffffu, s, d);
            if (lane >= d) s += n;
        }
        wsum[lane] = s;
    }
    __syncthreads();
    int excl = v - c + (wid ? wsum[wid - 1] : 0);
    g_offs[t] = excl;
    if (t == OUTDIM - 1) g_offs[OUTDIM] = excl + c;
}

// -------- 4. scatter nnz into CSR order --------
__global__ void k_scatter(const int* __restrict__ ind_in, const int* __restrict__ ind_out,
                          const float* __restrict__ wgt, int nnz) {
    int i = blockIdx.x * blockDim.x + threadIdx.x;
    if (i < nnz) {
        int o = ind_out[i];
        int p = g_offs[o] + atomicAdd(&g_cur[o], 1);
        g_meta[p] = make_uint2(__float_as_uint(wgt[i]), (unsigned)ind_in[i]);
    }
}

// -------- 5. transpose input [4096,1024] -> inT [1024,4096] --------
__global__ void k_transpose(const float* __restrict__ in) {
    __shared__ float tile[32][33];
    int x  = blockIdx.x * 32 + threadIdx.x;   // input column
    int y0 = blockIdx.y * 32;                 // input row base
#pragma unroll
    for (int i = threadIdx.y; i < 32; i += 8)
        tile[i][threadIdx.x] = in[(size_t)(y0 + i) * INDIM + x];
    __syncthreads();
    int b  = blockIdx.y * 32 + threadIdx.x;   // batch index (contig in inT)
    int c0 = blockIdx.x * 32;
#pragma unroll
    for (int i = threadIdx.y; i < 32; i += 8)
        g_inT[(size_t)(c0 + i) * BATCH + b] = tile[threadIdx.x][i];
}

// -------- 6. main SpMM --------
// Warp unit: 128 batch lanes (float4/thread) x 8 output columns.
// Register accumulation per column; results staged in a per-warp smem tile
// and written back transposed (coalesced 32B segments into d_out rows).
__global__ void __launch_bounds__(256) k_spmm(const float* __restrict__ bias,
                                              float* __restrict__ out) {
    __shared__ __align__(16) float buf[8][8][132];  // [warp][col][batch lane], padded
    int w = threadIdx.x >> 5, lane = threadIdx.x & 31;
    int chunk = blockIdx.y * 8 + w;           // 0..127, 8 cols each
    int o0 = chunk * 8;
    int wbase = blockIdx.x * 32 + lane;       // float4 index within an inT row
    const float4* inT4 = (const float4*)g_inT;

    for (int c = 0; c < 8; c++) {
        int o = o0 + c;
        int s = g_offs[o], e = g_offs[o + 1];
        float4 a0 = make_float4(0.f, 0.f, 0.f, 0.f);
        float4 a1 = make_float4(0.f, 0.f, 0.f, 0.f);
        int j = s;
        for (; j + 2 <= e; j += 2) {
            uint2 m0 = __ldg(&g_meta[j]);
            uint2 m1 = __ldg(&g_meta[j + 1]);
            float4 x0 = __ldg(&inT4[(m0.y << 10) + wbase]);
            float4 x1 = __ldg(&inT4[(m1.y << 10) + wbase]);
            float w0 = __uint_as_float(m0.x);
            float w1 = __uint_as_float(m1.x);
            a0.x = fmaf(w0, x0.x, a0.x); a0.y = fmaf(w0, x0.y, a0.y);
            a0.z = fmaf(w0, x0.z, a0.z); a0.w = fmaf(w0, x0.w, a0.w);
            a1.x = fmaf(w1, x1.x, a1.x); a1.y = fmaf(w1, x1.y, a1.y);
            a1.z = fmaf(w1, x1.z, a1.z); a1.w = fmaf(w1, x1.w, a1.w);
        }
        if (j < e) {
            uint2 m0 = __ldg(&g_meta[j]);
            float4 x0 = __ldg(&inT4[(m0.y << 10) + wbase]);
            float w0 = __uint_as_float(m0.x);
            a0.x = fmaf(w0, x0.x, a0.x); a0.y = fmaf(w0, x0.y, a0.y);
            a0.z = fmaf(w0, x0.z, a0.z); a0.w = fmaf(w0, x0.w, a0.w);
        }
        float4 a = make_float4(a0.x + a1.x, a0.y + a1.y, a0.z + a1.z, a0.w + a1.w);
        *(float4*)&buf[w][c][lane * 4] = a;
    }
    __syncwarp();

    const float4* bias4 = (const float4*)bias;
    float4 b0 = __ldg(&bias4[chunk * 2]);
    float4 b1 = __ldg(&bias4[chunk * 2 + 1]);
    int bbase = blockIdx.x * 128;
#pragma unroll
    for (int k = 0; k < 8; k++) {
        int u = k * 32 + lane;
        int row = u >> 1;   // batch lane 0..127
        int q   = u & 1;    // which float4 of the 8-col strip
        float4 v;
        v.x = buf[w][q * 4 + 0][row];
        v.y = buf[w][q * 4 + 1][row];
        v.z = buf[w][q * 4 + 2][row];
        v.w = buf[w][q * 4 + 3][row];
        float4 bb = q ? b1 : b0;
        v.x += bb.x; v.y += bb.y; v.z += bb.z; v.w += bb.w;
        *(float4*)&out[(size_t)(bbase + row) * OUTDIM + o0 + q * 4] = v;
    }
}

// -------- launch --------
extern "C" void kernel_launch(void* const* d_in, const int* in_sizes, int n_in,
                              void* d_out, int out_size) {
    const float* input  = (const float*)d_in[0];
    const float* weight = (const float*)d_in[1];
    const float* bias   = (const float*)d_in[2];
    const int*   ind_in = (const int*)d_in[3];
    const int*   ind_out= (const int*)d_in[4];
    int nnz = in_sizes[1];
    float* out = (float*)d_out;

    k_zero<<<1, OUTDIM>>>();
    k_hist<<<(nnz + 255) / 256, 256>>>(ind_out, nnz);
    k_scan<<<1, OUTDIM>>>();
    k_scatter<<<(nnz + 255) / 256, 256>>>(ind_in, ind_out, weight, nnz);
    k_transpose<<<dim3(INDIM / 32, BATCH / 32), dim3(32, 8)>>>(input);
    k_spmm<<<dim3(BATCH / 128, 16), 256>>>(bias, out);
}